// round 6
// baseline (speedup 1.0000x reference)
#include <cuda_runtime.h>
#include <math.h>
#include <stdint.h>

#define BB 8
#define D 768
#define NH 12
#define DH 64
#define HW 1024
#define G 5
#define S 1029           // G + HW
#define M_TOT (BB * S)   // 8232

// ---------------- scratch (static device globals) -------------------------------
__device__ float    g_xwt  [(size_t)M_TOT * D];
__device__ uint32_t g_xwt32[(size_t)M_TOT * D];
__device__ uint32_t g_qkv  [(size_t)M_TOT * 3 * D];
__device__ uint32_t g_o    [(size_t)M_TOT * D];
__device__ float    g_y    [(size_t)M_TOT * D];
__device__ uint32_t g_z32  [(size_t)M_TOT * D];
__device__ uint32_t g_h32  [(size_t)M_TOT * 4 * D];
__device__ float    g_y2   [(size_t)M_TOT * D];

__device__ uint32_t g_wqkv32[3 * D * D];
__device__ uint32_t g_wout32[D * D];
__device__ uint32_t g_w132  [4 * D * D];
__device__ uint32_t g_w232  [4 * D * D];

__device__ __forceinline__ uint32_t f2tf32(float x) {
    uint32_t r;
    asm("cvt.rna.tf32.f32 %0, %1;" : "=r"(r) : "f"(x));
    return r;
}
__device__ __forceinline__ void cp_async16(uint32_t dst_smem, const void* src, int src_bytes) {
    asm volatile("cp.async.cg.shared.global [%0], [%1], 16, %2;"
                 :: "r"(dst_smem), "l"(src), "r"(src_bytes));
}
__device__ __forceinline__ void cp_commit() { asm volatile("cp.async.commit_group;"); }
template<int N>
__device__ __forceinline__ void cp_wait() { asm volatile("cp.async.wait_group %0;" :: "n"(N)); }

__device__ __forceinline__ void mma_tf32(float* c, const uint32_t* a, const uint32_t* b) {
    asm volatile(
        "mma.sync.aligned.m16n8k8.row.col.f32.tf32.tf32.f32 "
        "{%0,%1,%2,%3}, {%4,%5,%6,%7}, {%8,%9}, {%0,%1,%2,%3};"
        : "+f"(c[0]), "+f"(c[1]), "+f"(c[2]), "+f"(c[3])
        : "r"(a[0]), "r"(a[1]), "r"(a[2]), "r"(a[3]), "r"(b[0]), "r"(b[1]));
}

// ---------------- weight conversion ----------------------------------------------
__global__ void __launch_bounds__(256) convert_weights_kernel(
    const float* __restrict__ wqkv, const float* __restrict__ wout,
    const float* __restrict__ w1, const float* __restrict__ w2)
{
    int i = blockIdx.x * 256 + threadIdx.x;
    if (i < 3 * D * D) g_wqkv32[i] = f2tf32(wqkv[i]);
    if (i < D * D)     g_wout32[i] = f2tf32(wout[i]);
    if (i < 4 * D * D) {
        g_w132[i] = f2tf32(w1[i]);
        g_w232[i] = f2tf32(w2[i]);
    }
}

// ---------------- block reduce over 256 threads ----------------------------------
__device__ __forceinline__ void block_reduce2(float& a, float& b2) {
    #pragma unroll
    for (int o = 16; o > 0; o >>= 1) {
        a  += __shfl_down_sync(0xFFFFFFFFu, a, o);
        b2 += __shfl_down_sync(0xFFFFFFFFu, b2, o);
    }
    __shared__ float sa[8], sb[8];
    int w = threadIdx.x >> 5, l = threadIdx.x & 31;
    if (l == 0) { sa[w] = a; sb[w] = b2; }
    __syncthreads();
    if (threadIdx.x < 8) {
        a = sa[threadIdx.x]; b2 = sb[threadIdx.x];
        #pragma unroll
        for (int o = 4; o > 0; o >>= 1) {
            a  += __shfl_down_sync(0xFFu, a, o);
            b2 += __shfl_down_sync(0xFFu, b2, o);
        }
        if (threadIdx.x == 0) { sa[0] = a; sb[0] = b2; }
    }
    __syncthreads();
    a = sa[0]; b2 = sb[0];
}

// ---------------- build feature rows: coalesced transpose + LN1 ------------------
#define BF_STRIDE 769
#define BUILD_SMEM (32 * BF_STRIDE * 4)

__global__ void __launch_bounds__(256) build_feat_kernel(
    const float* __restrict__ x,
    const float* __restrict__ gs, const float* __restrict__ gb)
{
    extern __shared__ float ts[];
    __shared__ float smean[32], srstd[32];
    int pt = blockIdx.x, b = blockIdx.y;
    int tid = threadIdx.x;
    int p0 = pt * 32;

    #pragma unroll 8
    for (int i = 0; i < 96; i++) {
        int e = i * 256 + tid;
        int k = e >> 5, p = e & 31;
        ts[p * BF_STRIDE + k] = x[((size_t)b * D + k) * HW + p0 + p];
    }
    __syncthreads();

    {
        int r = tid >> 3, sub = tid & 7;
        float s = 0.f, s2 = 0.f;
        #pragma unroll 8
        for (int j = 0; j < 96; j++) {
            float v = ts[r * BF_STRIDE + sub + 8 * j];
            s += v; s2 += v * v;
        }
        #pragma unroll
        for (int o = 4; o > 0; o >>= 1) {
            s  += __shfl_xor_sync(0xFFFFFFFFu, s, o);
            s2 += __shfl_xor_sync(0xFFFFFFFFu, s2, o);
        }
        if (sub == 0) {
            float mean = s * (1.0f / D);
            float var  = s2 * (1.0f / D) - mean * mean;
            smean[r] = mean;
            srstd[r] = rsqrtf(var + 1e-5f);
        }
    }
    __syncthreads();

    #pragma unroll 8
    for (int i = 0; i < 96; i++) {
        int p = i / 3;
        int k = (i % 3) * 256 + tid;
        float v = (ts[p * BF_STRIDE + k] - smean[p]) * srstd[p] * gs[k] + gb[k];
        size_t row = (size_t)(b * S + G + p0 + p);
        g_xwt  [row * D + k] = v;
        g_xwt32[row * D + k] = f2tf32(v);
    }
}

// ---------------- build token rows (ctx + registers + PE + LN1) ------------------
__global__ void __launch_bounds__(256) build_tok_kernel(
    const float* __restrict__ ctx, const float* __restrict__ regs,
    const float* __restrict__ gs, const float* __restrict__ gb)
{
    int blk = blockIdx.x;             // 0..BB*G-1
    int b = blk / G, sIdx = blk % G;
    int tid = threadIdx.x;

    float vals[3];
    float s = 0.f, s2 = 0.f;
    #pragma unroll
    for (int i = 0; i < 3; i++) {
        int k = tid + i * 256;
        float base = (sIdx == 0) ? ctx[k] : regs[(sIdx - 1) * D + k];
        float expo = (float)(2 * (k / 2)) / (float)D;
        float denom = powf(10000.0f, expo);
        float angle = (float)sIdx / denom;
        float pe = (k & 1) ? cosf(angle) : sinf(angle);
        float v = base + pe;
        vals[i] = v;
        s += v; s2 += v * v;
    }
    block_reduce2(s, s2);
    float mean = s * (1.0f / D);
    float var  = s2 * (1.0f / D) - mean * mean;
    float rstd = rsqrtf(var + 1e-5f);
    size_t row = (size_t)(b * S + sIdx);
    #pragma unroll
    for (int i = 0; i < 3; i++) {
        int k = tid + i * 256;
        float v = (vals[i] - mean) * rstd * gs[k] + gb[k];
        g_xwt  [row * D + k] = v;
        g_xwt32[row * D + k] = f2tf32(v);
    }
}

// ---------------- LN2 (writes tf32 bits) -----------------------------------------
__global__ void __launch_bounds__(256) ln_kernel(
    const float* __restrict__ in, const float* __restrict__ gs,
    const float* __restrict__ gb, uint32_t* __restrict__ out)
{
    int row = blockIdx.x;
    const float* p = in + (size_t)row * D;
    int tid = threadIdx.x;
    float vals[3];
    float s = 0.f, s2 = 0.f;
    #pragma unroll
    for (int i = 0; i < 3; i++) {
        float v = p[tid + i * 256];
        vals[i] = v; s += v; s2 += v * v;
    }
    block_reduce2(s, s2);
    float mean = s * (1.0f / D);
    float var  = s2 * (1.0f / D) - mean * mean;
    float rstd = rsqrtf(var + 1e-5f);
    #pragma unroll
    for (int i = 0; i < 3; i++) {
        int k = tid + i * 256;
        out[(size_t)row * D + k] = f2tf32((vals[i] - mean) * rstd * gs[k] + gb[k]);
    }
}

// ---------------- TF32 GEMM: 128x128 CTA, 8 warps of 64x32, 3-stage cp.async -----
// Round-4 proven shape; single barrier per k-tile (leading sync orders stage reuse).
#define KT 32
#define AST 36
#define GEMM_SMEM (3 * 2 * 128 * AST * 4)

template<bool GELU, bool RESID, bool OUT32>
__global__ void __launch_bounds__(256, 2) gemm_tf32(
    const uint32_t* __restrict__ A, const uint32_t* __restrict__ W,
    const float* __restrict__ bias, const float* __restrict__ Rz,
    float* __restrict__ C, int Mm, int Nn, int Kk)
{
    extern __shared__ uint32_t smu[];
    const int BUF = 128 * AST;

    int m0 = blockIdx.y * 128, n0 = blockIdx.x * 128;
    int tid = threadIdx.x;
    int warp = tid >> 5, lane = tid & 31;
    int g = lane >> 2, t = lane & 3;
    int wm = warp >> 2, wn = warp & 3;      // 2x4 warps, 64x32 each

    float acc[4][4][4];
    #pragma unroll
    for (int i = 0; i < 4; i++)
        #pragma unroll
        for (int j = 0; j < 4; j++)
            #pragma unroll
            for (int c = 0; c < 4; c++) acc[i][j][c] = 0.f;

    int lm = tid >> 1;
    int lc = (tid & 1) * 4;

    uint32_t smem_base = (uint32_t)__cvta_generic_to_shared(smu);
    const int ntiles = Kk / KT;

    auto load_stage = [&](int it, int stage) {
        int kt = it * KT;
        #pragma unroll
        for (int i = 0; i < 4; i++) {
            int c = lc + ((i & 1) ? 16 : 0) + ((i >> 1) ? 8 : 0);
            uint32_t dstA = smem_base + (stage * 2 * BUF + lm * AST + c) * 4;
            cp_async16(dstA, &A[(size_t)(m0 + lm) * Kk + kt + c],
                       (m0 + lm < Mm) ? 16 : 0);
            uint32_t dstB = smem_base + (stage * 2 * BUF + BUF + lm * AST + c) * 4;
            cp_async16(dstB, &W[(size_t)(n0 + lm) * Kk + kt + c], 16);
        }
        cp_commit();
    };

    load_stage(0, 0);
    load_stage(1, 1);

    for (int it = 0; it < ntiles; it++) {
        if (it + 1 < ntiles) cp_wait<1>(); else cp_wait<0>();
        __syncthreads();           // orders: prior-iter reads done before stage reuse below
        if (it + 2 < ntiles) {
            int st = it + 2; st -= (st / 3) * 3;
            load_stage(it + 2, st);
        }

        int cs = it - (it / 3) * 3;
        const uint32_t* Ab = smu + cs * 2 * BUF;
        const uint32_t* Bb = Ab + BUF;

        #pragma unroll
        for (int ks = 0; ks < KT; ks += 8) {
            uint32_t af[4][4], bf[4][2];
            #pragma unroll
            for (int mt = 0; mt < 4; mt++) {
                int m = wm * 64 + mt * 16 + g;
                af[mt][0] = Ab[m * AST + ks + t];
                af[mt][1] = Ab[(m + 8) * AST + ks + t];
                af[mt][2] = Ab[m * AST + ks + t + 4];
                af[mt][3] = Ab[(m + 8) * AST + ks + t + 4];
            }
            #pragma unroll
            for (int nt = 0; nt < 4; nt++) {
                int n = wn * 32 + nt * 8 + g;
                bf[nt][0] = Bb[n * AST + ks + t];
                bf[nt][1] = Bb[n * AST + ks + t + 4];
            }
            #pragma unroll
            for (int mt = 0; mt < 4; mt++)
                #pragma unroll
                for (int nt = 0; nt < 4; nt++)
                    mma_tf32(acc[mt][nt], af[mt], bf[nt]);
        }
        // no trailing barrier: leading barrier of the next iteration protects
        // stage (it)%3, which is first overwritten by the load issued at it+1.
    }

    // ---- epilogue ----
    #pragma unroll
    for (int mt = 0; mt < 4; mt++) {
        #pragma unroll
        for (int nt = 0; nt < 4; nt++) {
            int n = n0 + wn * 32 + nt * 8 + t * 2;
            float b0 = bias[n], b1 = bias[n + 1];
            #pragma unroll
            for (int half = 0; half < 2; half++) {
                int m = m0 + wm * 64 + mt * 16 + g + half * 8;
                if (m >= Mm) continue;
                float v0 = acc[mt][nt][half * 2 + 0] + b0;
                float v1 = acc[mt][nt][half * 2 + 1] + b1;
                if (GELU) {
                    v0 = 0.5f * v0 * (1.0f + erff(v0 * 0.70710678118654752f));
                    v1 = 0.5f * v1 * (1.0f + erff(v1 * 0.70710678118654752f));
                }
                if (RESID) {
                    float2 r = *(const float2*)&Rz[(size_t)m * Nn + n];
                    v0 += r.x; v1 += r.y;
                }
                if (OUT32) {
                    uint2 o = make_uint2(f2tf32(v0), f2tf32(v1));
                    *(uint2*)&((uint32_t*)C)[(size_t)m * Nn + n] = o;
                } else {
                    *(float2*)&C[(size_t)m * Nn + n] = make_float2(v0, v1);
                }
            }
        }
    }
}

// ---------------- flash attention v2: q-tile 128, double-buffered K/V ------------
#define KST 68
#define ATK (64 * KST)
#define ATTN_SMEM ((4 * ATK + 128 * KST) * 4)

__global__ void __launch_bounds__(128, 2) attn_mma_kernel()
{
    extern __shared__ uint32_t asmu[];
    float* Ps = (float*)(asmu + 4 * ATK);

    int qt = blockIdx.x, h = blockIdx.y, b = blockIdx.z;
    int tid = threadIdx.x;
    int warp = tid >> 5, lane = tid & 31;
    int g = lane >> 2, t = lane & 3;

    uint32_t smem_base = (uint32_t)__cvta_generic_to_shared(asmu);

    int rbase = qt * 128 + warp * 16 + g;

    uint32_t qf[2][8][4];
    #pragma unroll
    for (int mg = 0; mg < 2; mg++) {
        int r0 = rbase + mg * 64, r1 = r0 + 8;
        bool v0 = r0 < S, v1 = r1 < S;
        const uint32_t* q0 = g_qkv + ((size_t)(b * S) + (v0 ? r0 : 0)) * (3 * D) + h * DH;
        const uint32_t* q1 = g_qkv + ((size_t)(b * S) + (v1 ? r1 : 0)) * (3 * D) + h * DH;
        #pragma unroll
        for (int ks = 0; ks < 8; ks++) {
            int k0 = ks * 8 + t;
            qf[mg][ks][0] = v0 ? q0[k0] : 0u;
            qf[mg][ks][1] = v1 ? q1[k0] : 0u;
            qf[mg][ks][2] = v0 ? q0[k0 + 4] : 0u;
            qf[mg][ks][3] = v1 ? q1[k0 + 4] : 0u;
        }
    }

    float oacc[2][8][4];
    #pragma unroll
    for (int mg = 0; mg < 2; mg++)
        #pragma unroll
        for (int i = 0; i < 8; i++)
            #pragma unroll
            for (int c = 0; c < 4; c++) oacc[mg][i][c] = 0.f;
    float mr[2][2], lr[2][2];
    #pragma unroll
    for (int mg = 0; mg < 2; mg++) {
        mr[mg][0] = mr[mg][1] = -1e30f;
        lr[mg][0] = lr[mg][1] = 0.f;
    }

    const int NT = (S + 63) / 64;

    auto load_kv = [&](int kt, int st) {
        #pragma unroll
        for (int i = 0; i < 8; i++) {
            int idx = tid + i * 128;
            int r = idx >> 4, c4 = (idx & 15) * 4;
            int ki = kt * 64 + r;
            int bytes = (ki < S) ? 16 : 0;
            const uint32_t* base = g_qkv +
                ((size_t)(b * S) + (ki < S ? ki : 0)) * (3 * D) + h * DH + c4;
            cp_async16(smem_base + (st * 2 * ATK + r * KST + c4) * 4, base + D, bytes);
            cp_async16(smem_base + (st * 2 * ATK + ATK + r * KST + c4) * 4, base + 2 * D, bytes);
        }
        cp_commit();
    };

    load_kv(0, 0);

    for (int kt = 0; kt < NT; kt++) {
        if (kt + 1 < NT) { load_kv(kt + 1, (kt + 1) & 1); cp_wait<1>(); }
        else             { cp_wait<0>(); }
        __syncthreads();

        const uint32_t* Ks = asmu + (kt & 1) * 2 * ATK;
        const uint32_t* Vs = Ks + ATK;

        float sacc[2][8][4];
        #pragma unroll
        for (int mg = 0; mg < 2; mg++)
            #pragma unroll
            for (int nt = 0; nt < 8; nt++)
                #pragma unroll
                for (int c = 0; c < 4; c++) sacc[mg][nt][c] = 0.f;

        #pragma unroll
        for (int ks = 0; ks < 8; ks++) {
            #pragma unroll
            for (int nt = 0; nt < 8; nt++) {
                uint32_t bf[2];
                bf[0] = Ks[(nt * 8 + g) * KST + ks * 8 + t];
                bf[1] = Ks[(nt * 8 + g) * KST + ks * 8 + t + 4];
                mma_tf32(sacc[0][nt], qf[0][ks], bf);
                mma_tf32(sacc[1][nt], qf[1][ks], bf);
            }
        }

        #pragma unroll
        for (int mg = 0; mg < 2; mg++) {
            int r0 = rbase + mg * 64, r1 = r0 + 8;
            bool feat0 = r0 >= G, feat1 = r1 >= G;
            float mx0 = -1e30f, mx1 = -1e30f;
            #pragma unroll
            for (int nt = 0; nt < 8; nt++) {
                #pragma unroll
                for (int c = 0; c < 4; c++) {
                    int col = kt * 64 + nt * 8 + 2 * t + (c & 1);
                    float v = sacc[mg][nt][c] * 0.125f;
                    bool bad = (col >= S) || ((c < 2 ? feat0 : feat1) && col < G);
                    sacc[mg][nt][c] = bad ? -1e30f : v;
                }
                mx0 = fmaxf(mx0, fmaxf(sacc[mg][nt][0], sacc[mg][nt][1]));
                mx1 = fmaxf(mx1, fmaxf(sacc[mg][nt][2], sacc[mg][nt][3]));
            }
            mx0 = fmaxf(mx0, __shfl_xor_sync(0xFFFFFFFFu, mx0, 1));
            mx0 = fmaxf(mx0, __shfl_xor_sync(0xFFFFFFFFu, mx0, 2));
            mx1 = fmaxf(mx1, __shfl_xor_sync(0xFFFFFFFFu, mx1, 1));
            mx1 = fmaxf(mx1, __shfl_xor_sync(0xFFFFFFFFu, mx1, 2));

            float mn0 = fmaxf(mr[mg][0], mx0), mn1 = fmaxf(mr[mg][1], mx1);
            float sc0 = __expf(mr[mg][0] - mn0), sc1 = __expf(mr[mg][1] - mn1);
            mr[mg][0] = mn0; mr[mg][1] = mn1;

            float ls0 = 0.f, ls1 = 0.f;
            int prow0 = (mg * 64 + warp * 16 + g) * KST;
            int prow1 = prow0 + 8 * KST;
            #pragma unroll
            for (int nt = 0; nt < 8; nt++) {
                float p0 = __expf(sacc[mg][nt][0] - mn0);
                float p1 = __expf(sacc[mg][nt][1] - mn0);
                float p2 = __expf(sacc[mg][nt][2] - mn1);
                float p3 = __expf(sacc[mg][nt][3] - mn1);
                ls0 += p0 + p1; ls1 += p2 + p3;
                *(float2*)&Ps[prow0 + nt * 8 + 2 * t] = make_float2(p0, p1);
                *(float2*)&Ps[prow1 + nt * 8 + 2 * t] = make_float2(p2, p3);
                #pragma unroll
                for (int c = 0; c < 4; c++)
                    oacc[mg][nt][c] *= (c < 2) ? sc0 : sc1;
            }
            ls0 += __shfl_xor_sync(0xFFFFFFFFu, ls0, 1);
            ls0 += __shfl_xor_sync(0xFFFFFFFFu, ls0, 2);
            ls1 += __shfl_xor_sync(0xFFFFFFFFu, ls1, 1);
            ls1 += __shfl_xor_sync(0xFFFFFFFFu, ls1, 2);
            lr[mg][0] = lr[mg][0] * sc0 + ls0;
            lr[mg][1] = lr[mg][1] * sc1 + ls1;
        }
        __syncwarp();

        #pragma unroll
        for (int ks = 0; ks < 8; ks++) {
            uint32_t vf[8][2];
            #pragma unroll
            for (int nt = 0; nt < 8; nt++) {
                vf[nt][0] = Vs[(ks * 8 + t) * KST + nt * 8 + g];
                vf[nt][1] = Vs[(ks * 8 + t + 4) * KST + nt * 8 + g];
            }
            #pragma unroll
            for (int mg = 0; mg < 2; mg++) {
                int prow0 = (mg * 64 + warp * 16 + g) * KST;
                int prow1 = prow0 + 8 * KST;
                uint32_t pf[4];
                pf[0] = f2tf32(Ps[prow0 + ks * 8 + t]);
                pf[1] = f2tf32(Ps[prow1 + ks * 8 + t]);
                pf[2] = f2tf32(Ps[prow0 + ks * 8 + t + 4]);
                pf[3] = f2tf32(Ps[prow1 + ks * 8 + t + 4]);
                #pragma unroll
                for (int nt = 0; nt < 8; nt++)
                    mma_tf32(oacc[mg][nt], pf, vf[nt]);
            }
        }
        __syncthreads();
    }

    #pragma unroll
    for (int mg = 0; mg < 2; mg++) {
        int r0 = rbase + mg * 64, r1 = r0 + 8;
        bool v0 = r0 < S, v1 = r1 < S;
        float inv0 = 1.0f / lr[mg][0], inv1 = 1.0f / lr[mg][1];
        uint32_t* o0 = g_o + ((size_t)(b * S) + (v0 ? r0 : 0)) * D + h * DH;
        uint32_t* o1 = g_o + ((size_t)(b * S) + (v1 ? r1 : 0)) * D + h * DH;
        #pragma unroll
        for (int nt = 0; nt < 8; nt++) {
            int cbase = nt * 8 + 2 * t;
            if (v0) {
                o0[cbase]     = f2tf32(oacc[mg][nt][0] * inv0);
                o0[cbase + 1] = f2tf32(oacc[mg][nt][1] * inv0);
            }
            if (v1) {
                o1[cbase]     = f2tf32(oacc[mg][nt][2] * inv1);
                o1[cbase + 1] = f2tf32(oacc[mg][nt][3] * inv1);
            }
        }
    }
}

// ---------------- scatter: feature (smem transpose) + tokens ---------------------
__global__ void __launch_bounds__(256) scatter_feat_kernel(float* __restrict__ out)
{
    __shared__ float ts[32 * 33];
    int pt = blockIdx.x, kt = blockIdx.y, b = blockIdx.z;
    int tid = threadIdx.x;
    int p0 = pt * 32, k0 = kt * 32;
    #pragma unroll
    for (int i = 0; i < 4; i++) {
        int e = i * 256 + tid;
        int p = e >> 5, k = e & 31;
        ts[p * 33 + k] = g_y2[((size_t)(b * S + G + p0 + p)) * D + k0 + k];
    }
    __syncthreads();
    #pragma unroll
    for (int i = 0; i < 4; i++) {
        int e = i * 256 + tid;
        int k = e >> 5, p = e & 31;
        out[((size_t)b * D + k0 + k) * HW + p0 + p] = ts[p * 33 + k];
    }
}

__global__ void __launch_bounds__(256) scatter_tok_kernel(float* __restrict__ out)
{
    const int FEAT = BB * D * HW;
    const int CTX  = BB * D;
    int r = blockIdx.x;
    int b = r / G, s = r % G;
    int tid = threadIdx.x;
    #pragma unroll
    for (int i = 0; i < 3; i++) {
        int k = tid + i * 256;
        float v = g_y2[((size_t)(b * S + s)) * D + k];
        if (s == 0) out[FEAT + b * D + k] = v;
        else        out[FEAT + CTX + ((size_t)b * 4 + (s - 1)) * D + k] = v;
    }
}

// ---------------- host launcher ---------------------------------------------------
extern "C" void kernel_launch(void* const* d_in, const int* in_sizes, int n_in,
                              void* d_out, int out_size)
{
    const float* x    = (const float*)d_in[0];
    const float* ctx  = (const float*)d_in[1];
    const float* regs = (const float*)d_in[2];
    const float* wqkv = (const float*)d_in[3];
    const float* bqkv = (const float*)d_in[4];
    const float* wout = (const float*)d_in[5];
    const float* bout = (const float*)d_in[6];
    const float* ln1s = (const float*)d_in[7];
    const float* ln1b = (const float*)d_in[8];
    const float* ln2s = (const float*)d_in[9];
    const float* ln2b = (const float*)d_in[10];
    const float* w1   = (const float*)d_in[11];
    const float* b1   = (const float*)d_in[12];
    const float* w2   = (const float*)d_in[13];
    const float* b2   = (const float*)d_in[14];
    float* out = (float*)d_out;
    (void)in_sizes; (void)n_in; (void)out_size;

    uint32_t *xwt32, *qkv, *o, *z32, *h32;
    uint32_t *wqkv32, *wout32, *w132, *w232;
    float *xwt, *y, *y2;
    cudaGetSymbolAddress((void**)&xwt,    g_xwt);
    cudaGetSymbolAddress((void**)&xwt32,  g_xwt32);
    cudaGetSymbolAddress((void**)&qkv,    g_qkv);
    cudaGetSymbolAddress((void**)&o,      g_o);
    cudaGetSymbolAddress((void**)&y,      g_y);
    cudaGetSymbolAddress((void**)&z32,    g_z32);
    cudaGetSymbolAddress((void**)&h32,    g_h32);
    cudaGetSymbolAddress((void**)&y2,     g_y2);
    cudaGetSymbolAddress((void**)&wqkv32, g_wqkv32);
    cudaGetSymbolAddress((void**)&wout32, g_wout32);
    cudaGetSymbolAddress((void**)&w132,   g_w132);
    cudaGetSymbolAddress((void**)&w232,   g_w232);

    cudaFuncSetAttribute(gemm_tf32<false, false, true>,
        cudaFuncAttributeMaxDynamicSharedMemorySize, GEMM_SMEM);
    cudaFuncSetAttribute(gemm_tf32<false, true, false>,
        cudaFuncAttributeMaxDynamicSharedMemorySize, GEMM_SMEM);
    cudaFuncSetAttribute(gemm_tf32<true, false, true>,
        cudaFuncAttributeMaxDynamicSharedMemorySize, GEMM_SMEM);
    cudaFuncSetAttribute(attn_mma_kernel,
        cudaFuncAttributeMaxDynamicSharedMemorySize, ATTN_SMEM);
    cudaFuncSetAttribute(build_feat_kernel,
        cudaFuncAttributeMaxDynamicSharedMemorySize, BUILD_SMEM);

    const int M = M_TOT;
    const int MG = (M + 127) / 128;            // 65

    convert_weights_kernel<<<(4 * D * D + 255) / 256, 256>>>(wqkv, wout, w1, w2);

    build_feat_kernel<<<dim3(HW / 32, BB), 256, BUILD_SMEM>>>(x, ln1s, ln1b);
    build_tok_kernel<<<BB * G, 256>>>(ctx, regs, ln1s, ln1b);

    gemm_tf32<false, false, true><<<dim3(3 * D / 128, MG), 256, GEMM_SMEM>>>(
        xwt32, wqkv32, bqkv, nullptr, (float*)qkv, M, 3 * D, D);

    attn_mma_kernel<<<dim3((S + 127) / 128, NH, BB), 128, ATTN_SMEM>>>();

    gemm_tf32<false, true, false><<<dim3(D / 128, MG), 256, GEMM_SMEM>>>(
        o, wout32, bout, xwt, y, M, D, D);

    ln_kernel<<<M, 256>>>(y, ln2s, ln2b, z32);

    gemm_tf32<true, false, true><<<dim3(4 * D / 128, MG), 256, GEMM_SMEM>>>(
        z32, w132, b1, nullptr, (float*)h32, M, 4 * D, D);

    gemm_tf32<false, true, false><<<dim3(D / 128, MG), 256, GEMM_SMEM>>>(
        h32, w232, b2, y, y2, M, D, 4 * D);

    scatter_feat_kernel<<<dim3(HW / 32, D / 32, BB), 256>>>(out);
    scatter_tok_kernel<<<BB * G, 256>>>(out);
}

// round 7
// speedup vs baseline: 1.5400x; 1.5400x over previous
#include <cuda_runtime.h>
#include <math.h>
#include <stdint.h>

#define BB 8
#define D 768
#define NH 12
#define DH 64
#define HW 1024
#define G 5
#define S 1029           // G + HW
#define M_TOT (BB * S)   // 8232

// ---------------- scratch (static device globals) -------------------------------
__device__ float    g_xwt  [(size_t)M_TOT * D];
__device__ uint32_t g_xwt32[(size_t)M_TOT * D];
__device__ uint32_t g_qkv  [(size_t)M_TOT * 3 * D];
__device__ uint32_t g_o    [(size_t)M_TOT * D];
__device__ float    g_y    [(size_t)M_TOT * D];
__device__ uint32_t g_z32  [(size_t)M_TOT * D];
__device__ uint32_t g_h32  [(size_t)M_TOT * 4 * D];
__device__ float    g_y2   [(size_t)M_TOT * D];

__device__ uint32_t g_wqkv32[3 * D * D];
__device__ uint32_t g_wout32[D * D];
__device__ uint32_t g_w132  [4 * D * D];
__device__ uint32_t g_w232  [4 * D * D];

__device__ __forceinline__ uint32_t f2tf32(float x) {
    uint32_t r;
    asm("cvt.rna.tf32.f32 %0, %1;" : "=r"(r) : "f"(x));
    return r;
}
__device__ __forceinline__ void cp_async16(uint32_t dst_smem, const void* src, int src_bytes) {
    asm volatile("cp.async.cg.shared.global [%0], [%1], 16, %2;"
                 :: "r"(dst_smem), "l"(src), "r"(src_bytes));
}
__device__ __forceinline__ void cp_commit() { asm volatile("cp.async.commit_group;"); }
template<int N>
__device__ __forceinline__ void cp_wait() { asm volatile("cp.async.wait_group %0;" :: "n"(N)); }

__device__ __forceinline__ void mma_tf32(float* c, const uint32_t* a, const uint32_t* b) {
    asm volatile(
        "mma.sync.aligned.m16n8k8.row.col.f32.tf32.tf32.f32 "
        "{%0,%1,%2,%3}, {%4,%5,%6,%7}, {%8,%9}, {%0,%1,%2,%3};"
        : "+f"(c[0]), "+f"(c[1]), "+f"(c[2]), "+f"(c[3])
        : "r"(a[0]), "r"(a[1]), "r"(a[2]), "r"(a[3]), "r"(b[0]), "r"(b[1]));
}

// ---------------- weight conversion ----------------------------------------------
__global__ void __launch_bounds__(256) convert_weights_kernel(
    const float* __restrict__ wqkv, const float* __restrict__ wout,
    const float* __restrict__ w1, const float* __restrict__ w2)
{
    int i = blockIdx.x * 256 + threadIdx.x;
    if (i < 3 * D * D) g_wqkv32[i] = f2tf32(wqkv[i]);
    if (i < D * D)     g_wout32[i] = f2tf32(wout[i]);
    if (i < 4 * D * D) {
        g_w132[i] = f2tf32(w1[i]);
        g_w232[i] = f2tf32(w2[i]);
    }
}

// ---------------- block reduce over 256 threads ----------------------------------
__device__ __forceinline__ void block_reduce2(float& a, float& b2) {
    #pragma unroll
    for (int o = 16; o > 0; o >>= 1) {
        a  += __shfl_down_sync(0xFFFFFFFFu, a, o);
        b2 += __shfl_down_sync(0xFFFFFFFFu, b2, o);
    }
    __shared__ float sa[8], sb[8];
    int w = threadIdx.x >> 5, l = threadIdx.x & 31;
    if (l == 0) { sa[w] = a; sb[w] = b2; }
    __syncthreads();
    if (threadIdx.x < 8) {
        a = sa[threadIdx.x]; b2 = sb[threadIdx.x];
        #pragma unroll
        for (int o = 4; o > 0; o >>= 1) {
            a  += __shfl_down_sync(0xFFu, a, o);
            b2 += __shfl_down_sync(0xFFu, b2, o);
        }
        if (threadIdx.x == 0) { sa[0] = a; sb[0] = b2; }
    }
    __syncthreads();
    a = sa[0]; b2 = sb[0];
}

// ---------------- build feature rows: coalesced transpose + LN1 ------------------
#define BF_STRIDE 769
#define BUILD_SMEM (32 * BF_STRIDE * 4)

__global__ void __launch_bounds__(256) build_feat_kernel(
    const float* __restrict__ x,
    const float* __restrict__ gs, const float* __restrict__ gb)
{
    extern __shared__ float ts[];
    __shared__ float smean[32], srstd[32];
    int pt = blockIdx.x, b = blockIdx.y;
    int tid = threadIdx.x;
    int p0 = pt * 32;

    #pragma unroll 8
    for (int i = 0; i < 96; i++) {
        int e = i * 256 + tid;
        int k = e >> 5, p = e & 31;
        ts[p * BF_STRIDE + k] = x[((size_t)b * D + k) * HW + p0 + p];
    }
    __syncthreads();

    {
        int r = tid >> 3, sub = tid & 7;
        float s = 0.f, s2 = 0.f;
        #pragma unroll 8
        for (int j = 0; j < 96; j++) {
            float v = ts[r * BF_STRIDE + sub + 8 * j];
            s += v; s2 += v * v;
        }
        #pragma unroll
        for (int o = 4; o > 0; o >>= 1) {
            s  += __shfl_xor_sync(0xFFFFFFFFu, s, o);
            s2 += __shfl_xor_sync(0xFFFFFFFFu, s2, o);
        }
        if (sub == 0) {
            float mean = s * (1.0f / D);
            float var  = s2 * (1.0f / D) - mean * mean;
            smean[r] = mean;
            srstd[r] = rsqrtf(var + 1e-5f);
        }
    }
    __syncthreads();

    #pragma unroll 8
    for (int i = 0; i < 96; i++) {
        int p = i / 3;
        int k = (i % 3) * 256 + tid;
        float v = (ts[p * BF_STRIDE + k] - smean[p]) * srstd[p] * gs[k] + gb[k];
        size_t row = (size_t)(b * S + G + p0 + p);
        g_xwt  [row * D + k] = v;
        g_xwt32[row * D + k] = f2tf32(v);
    }
}

// ---------------- build token rows (ctx + registers + PE + LN1) ------------------
__global__ void __launch_bounds__(256) build_tok_kernel(
    const float* __restrict__ ctx, const float* __restrict__ regs,
    const float* __restrict__ gs, const float* __restrict__ gb)
{
    int blk = blockIdx.x;             // 0..BB*G-1
    int b = blk / G, sIdx = blk % G;
    int tid = threadIdx.x;

    float vals[3];
    float s = 0.f, s2 = 0.f;
    #pragma unroll
    for (int i = 0; i < 3; i++) {
        int k = tid + i * 256;
        float base = (sIdx == 0) ? ctx[k] : regs[(sIdx - 1) * D + k];
        float expo = (float)(2 * (k / 2)) / (float)D;
        float denom = powf(10000.0f, expo);
        float angle = (float)sIdx / denom;
        float pe = (k & 1) ? cosf(angle) : sinf(angle);
        float v = base + pe;
        vals[i] = v;
        s += v; s2 += v * v;
    }
    block_reduce2(s, s2);
    float mean = s * (1.0f / D);
    float var  = s2 * (1.0f / D) - mean * mean;
    float rstd = rsqrtf(var + 1e-5f);
    size_t row = (size_t)(b * S + sIdx);
    #pragma unroll
    for (int i = 0; i < 3; i++) {
        int k = tid + i * 256;
        float v = (vals[i] - mean) * rstd * gs[k] + gb[k];
        g_xwt  [row * D + k] = v;
        g_xwt32[row * D + k] = f2tf32(v);
    }
}

// ---------------- LN2 (writes tf32 bits) -----------------------------------------
__global__ void __launch_bounds__(256) ln_kernel(
    const float* __restrict__ in, const float* __restrict__ gs,
    const float* __restrict__ gb, uint32_t* __restrict__ out)
{
    int row = blockIdx.x;
    const float* p = in + (size_t)row * D;
    int tid = threadIdx.x;
    float vals[3];
    float s = 0.f, s2 = 0.f;
    #pragma unroll
    for (int i = 0; i < 3; i++) {
        float v = p[tid + i * 256];
        vals[i] = v; s += v; s2 += v * v;
    }
    block_reduce2(s, s2);
    float mean = s * (1.0f / D);
    float var  = s2 * (1.0f / D) - mean * mean;
    float rstd = rsqrtf(var + 1e-5f);
    #pragma unroll
    for (int i = 0; i < 3; i++) {
        int k = tid + i * 256;
        out[(size_t)row * D + k] = f2tf32((vals[i] - mean) * rstd * gs[k] + gb[k]);
    }
}

// ---------------- TF32 GEMM: round-4 proven shape (verbatim) ---------------------
// 128x128 CTA, 8 warps (2x4) of 64x32, 3-stage cp.async, leading+trailing barriers.
#define KT 32
#define AST 36
#define GEMM_SMEM (3 * 2 * 128 * AST * 4)

template<bool GELU, bool RESID, bool OUT32>
__global__ void __launch_bounds__(256, 2) gemm_tf32(
    const uint32_t* __restrict__ A, const uint32_t* __restrict__ W,
    const float* __restrict__ bias, const float* __restrict__ Rz,
    float* __restrict__ C, int Mm, int Nn, int Kk)
{
    extern __shared__ uint32_t smu[];
    const int BUF = 128 * AST;

    int m0 = blockIdx.y * 128, n0 = blockIdx.x * 128;
    int tid = threadIdx.x;
    int warp = tid >> 5, lane = tid & 31;
    int g = lane >> 2, t = lane & 3;
    int wm = warp >> 2, wn = warp & 3;

    float acc[4][4][4];
    #pragma unroll
    for (int i = 0; i < 4; i++)
        #pragma unroll
        for (int j = 0; j < 4; j++)
            #pragma unroll
            for (int c = 0; c < 4; c++) acc[i][j][c] = 0.f;

    int lm = tid >> 1;
    int lc = (tid & 1) * 4;

    uint32_t smem_base = (uint32_t)__cvta_generic_to_shared(smu);
    const int ntiles = Kk / KT;

    auto load_stage = [&](int it, int stage) {
        int kt = it * KT;
        #pragma unroll
        for (int i = 0; i < 4; i++) {
            int c = lc + ((i & 1) ? 16 : 0) + ((i >> 1) ? 8 : 0);
            uint32_t dstA = smem_base + (stage * 2 * BUF + lm * AST + c) * 4;
            cp_async16(dstA, &A[(size_t)(m0 + lm) * Kk + kt + c],
                       (m0 + lm < Mm) ? 16 : 0);
            uint32_t dstB = smem_base + (stage * 2 * BUF + BUF + lm * AST + c) * 4;
            cp_async16(dstB, &W[(size_t)(n0 + lm) * Kk + kt + c], 16);
        }
        cp_commit();
    };

    load_stage(0, 0);
    load_stage(1, 1);

    for (int it = 0; it < ntiles; it++) {
        if (it + 1 < ntiles) cp_wait<1>(); else cp_wait<0>();
        __syncthreads();
        if (it + 2 < ntiles) {
            int st = it + 2; st -= (st / 3) * 3;
            load_stage(it + 2, st);
        }

        int cs = it - (it / 3) * 3;
        const uint32_t* Ab = smu + cs * 2 * BUF;
        const uint32_t* Bb = Ab + BUF;

        #pragma unroll
        for (int ks = 0; ks < KT; ks += 8) {
            uint32_t af[4][4], bf[4][2];
            #pragma unroll
            for (int mt = 0; mt < 4; mt++) {
                int m = wm * 64 + mt * 16 + g;
                af[mt][0] = Ab[m * AST + ks + t];
                af[mt][1] = Ab[(m + 8) * AST + ks + t];
                af[mt][2] = Ab[m * AST + ks + t + 4];
                af[mt][3] = Ab[(m + 8) * AST + ks + t + 4];
            }
            #pragma unroll
            for (int nt = 0; nt < 4; nt++) {
                int n = wn * 32 + nt * 8 + g;
                bf[nt][0] = Bb[n * AST + ks + t];
                bf[nt][1] = Bb[n * AST + ks + t + 4];
            }
            #pragma unroll
            for (int mt = 0; mt < 4; mt++)
                #pragma unroll
                for (int nt = 0; nt < 4; nt++)
                    mma_tf32(acc[mt][nt], af[mt], bf[nt]);
        }
        __syncthreads();   // pacing barrier — empirically load-bearing (r6 lesson)
    }

    // ---- epilogue ----
    #pragma unroll
    for (int mt = 0; mt < 4; mt++) {
        #pragma unroll
        for (int nt = 0; nt < 4; nt++) {
            int n = n0 + wn * 32 + nt * 8 + t * 2;
            float b0 = bias[n], b1 = bias[n + 1];
            #pragma unroll
            for (int half = 0; half < 2; half++) {
                int m = m0 + wm * 64 + mt * 16 + g + half * 8;
                if (m >= Mm) continue;
                float v0 = acc[mt][nt][half * 2 + 0] + b0;
                float v1 = acc[mt][nt][half * 2 + 1] + b1;
                if (GELU) {
                    v0 = 0.5f * v0 * (1.0f + erff(v0 * 0.70710678118654752f));
                    v1 = 0.5f * v1 * (1.0f + erff(v1 * 0.70710678118654752f));
                }
                if (RESID) {
                    float2 r = *(const float2*)&Rz[(size_t)m * Nn + n];
                    v0 += r.x; v1 += r.y;
                }
                if (OUT32) {
                    uint2 o = make_uint2(f2tf32(v0), f2tf32(v1));
                    *(uint2*)&((uint32_t*)C)[(size_t)m * Nn + n] = o;
                } else {
                    *(float2*)&C[(size_t)m * Nn + n] = make_float2(v0, v1);
                }
            }
        }
    }
}

// ---------------- flash attention v2: q-tile 128, double-buffered K/V ------------
#define KST 68
#define ATK (64 * KST)
#define ATTN_SMEM ((4 * ATK + 128 * KST) * 4)

__global__ void __launch_bounds__(128, 2) attn_mma_kernel()
{
    extern __shared__ uint32_t asmu[];
    float* Ps = (float*)(asmu + 4 * ATK);

    int qt = blockIdx.x, h = blockIdx.y, b = blockIdx.z;
    int tid = threadIdx.x;
    int warp = tid >> 5, lane = tid & 31;
    int g = lane >> 2, t = lane & 3;

    uint32_t smem_base = (uint32_t)__cvta_generic_to_shared(asmu);

    int rbase = qt * 128 + warp * 16 + g;

    uint32_t qf[2][8][4];
    #pragma unroll
    for (int mg = 0; mg < 2; mg++) {
        int r0 = rbase + mg * 64, r1 = r0 + 8;
        bool v0 = r0 < S, v1 = r1 < S;
        const uint32_t* q0 = g_qkv + ((size_t)(b * S) + (v0 ? r0 : 0)) * (3 * D) + h * DH;
        const uint32_t* q1 = g_qkv + ((size_t)(b * S) + (v1 ? r1 : 0)) * (3 * D) + h * DH;
        #pragma unroll
        for (int ks = 0; ks < 8; ks++) {
            int k0 = ks * 8 + t;
            qf[mg][ks][0] = v0 ? q0[k0] : 0u;
            qf[mg][ks][1] = v1 ? q1[k0] : 0u;
            qf[mg][ks][2] = v0 ? q0[k0 + 4] : 0u;
            qf[mg][ks][3] = v1 ? q1[k0 + 4] : 0u;
        }
    }

    float oacc[2][8][4];
    #pragma unroll
    for (int mg = 0; mg < 2; mg++)
        #pragma unroll
        for (int i = 0; i < 8; i++)
            #pragma unroll
            for (int c = 0; c < 4; c++) oacc[mg][i][c] = 0.f;
    float mr[2][2], lr[2][2];
    #pragma unroll
    for (int mg = 0; mg < 2; mg++) {
        mr[mg][0] = mr[mg][1] = -1e30f;
        lr[mg][0] = lr[mg][1] = 0.f;
    }

    const int NT = (S + 63) / 64;

    auto load_kv = [&](int kt, int st) {
        #pragma unroll
        for (int i = 0; i < 8; i++) {
            int idx = tid + i * 128;
            int r = idx >> 4, c4 = (idx & 15) * 4;
            int ki = kt * 64 + r;
            int bytes = (ki < S) ? 16 : 0;
            const uint32_t* base = g_qkv +
                ((size_t)(b * S) + (ki < S ? ki : 0)) * (3 * D) + h * DH + c4;
            cp_async16(smem_base + (st * 2 * ATK + r * KST + c4) * 4, base + D, bytes);
            cp_async16(smem_base + (st * 2 * ATK + ATK + r * KST + c4) * 4, base + 2 * D, bytes);
        }
        cp_commit();
    };

    load_kv(0, 0);

    for (int kt = 0; kt < NT; kt++) {
        if (kt + 1 < NT) { load_kv(kt + 1, (kt + 1) & 1); cp_wait<1>(); }
        else             { cp_wait<0>(); }
        __syncthreads();

        const uint32_t* Ks = asmu + (kt & 1) * 2 * ATK;
        const uint32_t* Vs = Ks + ATK;

        float sacc[2][8][4];
        #pragma unroll
        for (int mg = 0; mg < 2; mg++)
            #pragma unroll
            for (int nt = 0; nt < 8; nt++)
                #pragma unroll
                for (int c = 0; c < 4; c++) sacc[mg][nt][c] = 0.f;

        #pragma unroll
        for (int ks = 0; ks < 8; ks++) {
            #pragma unroll
            for (int nt = 0; nt < 8; nt++) {
                uint32_t bf[2];
                bf[0] = Ks[(nt * 8 + g) * KST + ks * 8 + t];
                bf[1] = Ks[(nt * 8 + g) * KST + ks * 8 + t + 4];
                mma_tf32(sacc[0][nt], qf[0][ks], bf);
                mma_tf32(sacc[1][nt], qf[1][ks], bf);
            }
        }

        #pragma unroll
        for (int mg = 0; mg < 2; mg++) {
            int r0 = rbase + mg * 64, r1 = r0 + 8;
            bool feat0 = r0 >= G, feat1 = r1 >= G;
            float mx0 = -1e30f, mx1 = -1e30f;
            #pragma unroll
            for (int nt = 0; nt < 8; nt++) {
                #pragma unroll
                for (int c = 0; c < 4; c++) {
                    int col = kt * 64 + nt * 8 + 2 * t + (c & 1);
                    float v = sacc[mg][nt][c] * 0.125f;
                    bool bad = (col >= S) || ((c < 2 ? feat0 : feat1) && col < G);
                    sacc[mg][nt][c] = bad ? -1e30f : v;
                }
                mx0 = fmaxf(mx0, fmaxf(sacc[mg][nt][0], sacc[mg][nt][1]));
                mx1 = fmaxf(mx1, fmaxf(sacc[mg][nt][2], sacc[mg][nt][3]));
            }
            mx0 = fmaxf(mx0, __shfl_xor_sync(0xFFFFFFFFu, mx0, 1));
            mx0 = fmaxf(mx0, __shfl_xor_sync(0xFFFFFFFFu, mx0, 2));
            mx1 = fmaxf(mx1, __shfl_xor_sync(0xFFFFFFFFu, mx1, 1));
            mx1 = fmaxf(mx1, __shfl_xor_sync(0xFFFFFFFFu, mx1, 2));

            float mn0 = fmaxf(mr[mg][0], mx0), mn1 = fmaxf(mr[mg][1], mx1);
            float sc0 = __expf(mr[mg][0] - mn0), sc1 = __expf(mr[mg][1] - mn1);
            mr[mg][0] = mn0; mr[mg][1] = mn1;

            float ls0 = 0.f, ls1 = 0.f;
            int prow0 = (mg * 64 + warp * 16 + g) * KST;
            int prow1 = prow0 + 8 * KST;
            #pragma unroll
            for (int nt = 0; nt < 8; nt++) {
                float p0 = __expf(sacc[mg][nt][0] - mn0);
                float p1 = __expf(sacc[mg][nt][1] - mn0);
                float p2 = __expf(sacc[mg][nt][2] - mn1);
                float p3 = __expf(sacc[mg][nt][3] - mn1);
                ls0 += p0 + p1; ls1 += p2 + p3;
                *(float2*)&Ps[prow0 + nt * 8 + 2 * t] = make_float2(p0, p1);
                *(float2*)&Ps[prow1 + nt * 8 + 2 * t] = make_float2(p2, p3);
                #pragma unroll
                for (int c = 0; c < 4; c++)
                    oacc[mg][nt][c] *= (c < 2) ? sc0 : sc1;
            }
            ls0 += __shfl_xor_sync(0xFFFFFFFFu, ls0, 1);
            ls0 += __shfl_xor_sync(0xFFFFFFFFu, ls0, 2);
            ls1 += __shfl_xor_sync(0xFFFFFFFFu, ls1, 1);
            ls1 += __shfl_xor_sync(0xFFFFFFFFu, ls1, 2);
            lr[mg][0] = lr[mg][0] * sc0 + ls0;
            lr[mg][1] = lr[mg][1] * sc1 + ls1;
        }
        __syncwarp();

        #pragma unroll
        for (int ks = 0; ks < 8; ks++) {
            uint32_t vf[8][2];
            #pragma unroll
            for (int nt = 0; nt < 8; nt++) {
                vf[nt][0] = Vs[(ks * 8 + t) * KST + nt * 8 + g];
                vf[nt][1] = Vs[(ks * 8 + t + 4) * KST + nt * 8 + g];
            }
            #pragma unroll
            for (int mg = 0; mg < 2; mg++) {
                int prow0 = (mg * 64 + warp * 16 + g) * KST;
                int prow1 = prow0 + 8 * KST;
                uint32_t pf[4];
                pf[0] = f2tf32(Ps[prow0 + ks * 8 + t]);
                pf[1] = f2tf32(Ps[prow1 + ks * 8 + t]);
                pf[2] = f2tf32(Ps[prow0 + ks * 8 + t + 4]);
                pf[3] = f2tf32(Ps[prow1 + ks * 8 + t + 4]);
                #pragma unroll
                for (int nt = 0; nt < 8; nt++)
                    mma_tf32(oacc[mg][nt], pf, vf[nt]);
            }
        }
        __syncthreads();
    }

    #pragma unroll
    for (int mg = 0; mg < 2; mg++) {
        int r0 = rbase + mg * 64, r1 = r0 + 8;
        bool v0 = r0 < S, v1 = r1 < S;
        float inv0 = 1.0f / lr[mg][0], inv1 = 1.0f / lr[mg][1];
        uint32_t* o0 = g_o + ((size_t)(b * S) + (v0 ? r0 : 0)) * D + h * DH;
        uint32_t* o1 = g_o + ((size_t)(b * S) + (v1 ? r1 : 0)) * D + h * DH;
        #pragma unroll
        for (int nt = 0; nt < 8; nt++) {
            int cbase = nt * 8 + 2 * t;
            if (v0) {
                o0[cbase]     = f2tf32(oacc[mg][nt][0] * inv0);
                o0[cbase + 1] = f2tf32(oacc[mg][nt][1] * inv0);
            }
            if (v1) {
                o1[cbase]     = f2tf32(oacc[mg][nt][2] * inv1);
                o1[cbase + 1] = f2tf32(oacc[mg][nt][3] * inv1);
            }
        }
    }
}

// ---------------- scatter: feature (smem transpose) + tokens ---------------------
__global__ void __launch_bounds__(256) scatter_feat_kernel(float* __restrict__ out)
{
    __shared__ float ts[32 * 33];
    int pt = blockIdx.x, kt = blockIdx.y, b = blockIdx.z;
    int tid = threadIdx.x;
    int p0 = pt * 32, k0 = kt * 32;
    #pragma unroll
    for (int i = 0; i < 4; i++) {
        int e = i * 256 + tid;
        int p = e >> 5, k = e & 31;
        ts[p * 33 + k] = g_y2[((size_t)(b * S + G + p0 + p)) * D + k0 + k];
    }
    __syncthreads();
    #pragma unroll
    for (int i = 0; i < 4; i++) {
        int e = i * 256 + tid;
        int k = e >> 5, p = e & 31;
        out[((size_t)b * D + k0 + k) * HW + p0 + p] = ts[p * 33 + k];
    }
}

__global__ void __launch_bounds__(256) scatter_tok_kernel(float* __restrict__ out)
{
    const int FEAT = BB * D * HW;
    const int CTX  = BB * D;
    int r = blockIdx.x;
    int b = r / G, s = r % G;
    int tid = threadIdx.x;
    #pragma unroll
    for (int i = 0; i < 3; i++) {
        int k = tid + i * 256;
        float v = g_y2[((size_t)(b * S + s)) * D + k];
        if (s == 0) out[FEAT + b * D + k] = v;
        else        out[FEAT + CTX + ((size_t)b * 4 + (s - 1)) * D + k] = v;
    }
}

// ---------------- host launcher ---------------------------------------------------
extern "C" void kernel_launch(void* const* d_in, const int* in_sizes, int n_in,
                              void* d_out, int out_size)
{
    const float* x    = (const float*)d_in[0];
    const float* ctx  = (const float*)d_in[1];
    const float* regs = (const float*)d_in[2];
    const float* wqkv = (const float*)d_in[3];
    const float* bqkv = (const float*)d_in[4];
    const float* wout = (const float*)d_in[5];
    const float* bout = (const float*)d_in[6];
    const float* ln1s = (const float*)d_in[7];
    const float* ln1b = (const float*)d_in[8];
    const float* ln2s = (const float*)d_in[9];
    const float* ln2b = (const float*)d_in[10];
    const float* w1   = (const float*)d_in[11];
    const float* b1   = (const float*)d_in[12];
    const float* w2   = (const float*)d_in[13];
    const float* b2   = (const float*)d_in[14];
    float* out = (float*)d_out;
    (void)in_sizes; (void)n_in; (void)out_size;

    uint32_t *xwt32, *qkv, *o, *z32, *h32;
    uint32_t *wqkv32, *wout32, *w132, *w232;
    float *xwt, *y, *y2;
    cudaGetSymbolAddress((void**)&xwt,    g_xwt);
    cudaGetSymbolAddress((void**)&xwt32,  g_xwt32);
    cudaGetSymbolAddress((void**)&qkv,    g_qkv);
    cudaGetSymbolAddress((void**)&o,      g_o);
    cudaGetSymbolAddress((void**)&y,      g_y);
    cudaGetSymbolAddress((void**)&z32,    g_z32);
    cudaGetSymbolAddress((void**)&h32,    g_h32);
    cudaGetSymbolAddress((void**)&y2,     g_y2);
    cudaGetSymbolAddress((void**)&wqkv32, g_wqkv32);
    cudaGetSymbolAddress((void**)&wout32, g_wout32);
    cudaGetSymbolAddress((void**)&w132,   g_w132);
    cudaGetSymbolAddress((void**)&w232,   g_w232);

    cudaFuncSetAttribute(gemm_tf32<false, false, true>,
        cudaFuncAttributeMaxDynamicSharedMemorySize, GEMM_SMEM);
    cudaFuncSetAttribute(gemm_tf32<false, true, false>,
        cudaFuncAttributeMaxDynamicSharedMemorySize, GEMM_SMEM);
    cudaFuncSetAttribute(gemm_tf32<true, false, true>,
        cudaFuncAttributeMaxDynamicSharedMemorySize, GEMM_SMEM);
    cudaFuncSetAttribute(attn_mma_kernel,
        cudaFuncAttributeMaxDynamicSharedMemorySize, ATTN_SMEM);
    cudaFuncSetAttribute(build_feat_kernel,
        cudaFuncAttributeMaxDynamicSharedMemorySize, BUILD_SMEM);

    const int M = M_TOT;
    const int MG = (M + 127) / 128;            // 65

    convert_weights_kernel<<<(4 * D * D + 255) / 256, 256>>>(wqkv, wout, w1, w2);

    build_feat_kernel<<<dim3(HW / 32, BB), 256, BUILD_SMEM>>>(x, ln1s, ln1b);
    build_tok_kernel<<<BB * G, 256>>>(ctx, regs, ln1s, ln1b);

    gemm_tf32<false, false, true><<<dim3(3 * D / 128, MG), 256, GEMM_SMEM>>>(
        xwt32, wqkv32, bqkv, nullptr, (float*)qkv, M, 3 * D, D);

    attn_mma_kernel<<<dim3((S + 127) / 128, NH, BB), 128, ATTN_SMEM>>>();

    gemm_tf32<false, true, false><<<dim3(D / 128, MG), 256, GEMM_SMEM>>>(
        o, wout32, bout, xwt, y, M, D, D);

    ln_kernel<<<M, 256>>>(y, ln2s, ln2b, z32);

    gemm_tf32<true, false, true><<<dim3(4 * D / 128, MG), 256, GEMM_SMEM>>>(
        z32, w132, b1, nullptr, (float*)h32, M, 4 * D, D);

    gemm_tf32<false, true, false><<<dim3(D / 128, MG), 256, GEMM_SMEM>>>(
        h32, w232, b2, y, y2, M, D, 4 * D);

    scatter_feat_kernel<<<dim3(HW / 32, D / 32, BB), 256>>>(out);
    scatter_tok_kernel<<<BB * G, 256>>>(out);
}